// round 14
// baseline (speedup 1.0000x reference)
#include <cuda_runtime.h>
#include <cuda_bf16.h>
#include <cstdint>

// Problem constants
#define B_    4
#define C_    256
#define CQ_   32
#define MID_  16
#define H_    56
#define W_    56
#define HW_   3136     // 56*56
#define N_TOT 12544    // B_*HW_

// Scratch (allocation-free: __device__ globals). 16B-aligned for uint4.
__device__ float g_gpk[CQ_ * 49];
__device__ float g_kmqm[B_ * 64 * HW_];
__device__ float g_pre[B_ * C_ * HW_];
__device__ __align__(16) __nv_bfloat16 g_pret_hi[N_TOT * C_];   // (n, c) K-major
__device__ __align__(16) __nv_bfloat16 g_pret_lo[N_TOT * C_];
__device__ __align__(16) __nv_bfloat16 g_wf_hi[C_ * C_];
__device__ __align__(16) __nv_bfloat16 g_wf_lo[C_ * C_];

__device__ __forceinline__ uint32_t smem_u32(const void* p) {
    uint32_t a;
    asm("{ .reg .u64 t; cvta.to.shared.u64 t, %1; cvt.u32.u64 %0, t; }" : "=r"(a) : "l"(p));
    return a;
}
__device__ __forceinline__ void ldsm_x4(uint32_t addr, uint32_t& r0, uint32_t& r1,
                                        uint32_t& r2, uint32_t& r3) {
    asm volatile("ldmatrix.sync.aligned.m8n8.x4.shared.b16 {%0,%1,%2,%3}, [%4];"
                 : "=r"(r0), "=r"(r1), "=r"(r2), "=r"(r3) : "r"(addr));
}
__device__ __forceinline__ void mma16816(float* d, const uint32_t* a, uint32_t b0, uint32_t b1) {
    asm volatile(
        "mma.sync.aligned.m16n8k16.row.col.f32.bf16.bf16.f32 "
        "{%0,%1,%2,%3}, {%4,%5,%6,%7}, {%8,%9}, {%0,%1,%2,%3};"
        : "+f"(d[0]), "+f"(d[1]), "+f"(d[2]), "+f"(d[3])
        : "r"(a[0]), "r"(a[1]), "r"(a[2]), "r"(a[3]), "r"(b0), "r"(b1));
}

// ---------------------------------------------------------------------------
// Geometry prior
__global__ void gpk_kernel(const float* __restrict__ wg1, const float* __restrict__ bg1,
                           const float* __restrict__ wg2, const float* __restrict__ bg2) {
    int idx = blockIdx.x * 256 + threadIdx.x;
    if (idx >= CQ_ * 49) return;
    int c = idx / 49, r = idx % 49, i = r / 7, j = r % 7;
    float xp = (float)(j - 3);
    float yp = (float)(3 - i);
    float acc = bg2[c];
#pragma unroll
    for (int o = 0; o < MID_; o++) {
        float g1 = fmaf(wg1[o * 2 + 0], xp, fmaf(wg1[o * 2 + 1], yp, bg1[o]));
        g1 = fmaxf(g1, 0.f);
        acc = fmaf(wg2[c * MID_ + o], g1, acc);
    }
    g_gpk[idx] = acc;
}

// ---------------------------------------------------------------------------
// Double-buffered SGEMM for km/qm (BM=64)
template<int BM>
__global__ void __launch_bounds__(256) gemm2(
    const float* __restrict__ W1, const float* __restrict__ W2, int split,
    const float* __restrict__ bias1, const float* __restrict__ bias2,
    const float* __restrict__ In, float* __restrict__ Out, int Cdim, int OC) {
    constexpr int TM = BM / 16;
    constexpr int NA = TM / 4;
    __shared__ float As[2][16][BM];
    __shared__ float Bs[2][16][64];

    int b = blockIdx.z;
    const float* Inb = In + (size_t)b * Cdim * HW_;
    float* Outb = Out + (size_t)b * OC * HW_;
    int ocBase = blockIdx.y * BM;
    int pBase  = blockIdx.x * 64;

    int tid = threadIdx.x;
    int tx = tid & 15, ty = tid >> 4;

    int arow, akb;
    if (BM == 128) { arow = tid >> 1; akb = (tid & 1) * 8; }
    else           { arow = tid >> 2; akb = (tid & 3) * 4; }
    int oc = ocBase + arow;
    const float* wrow = (oc < split) ? (W1 + (size_t)oc * Cdim)
                                     : (W2 + (size_t)(oc - split) * Cdim);
    int brow = tid >> 4, bcol = (tid & 15) * 4;
    const float* bptr = Inb + (size_t)brow * HW_ + pBase + bcol;

    float acc[TM][4];
#pragma unroll
    for (int i = 0; i < TM; i++)
#pragma unroll
        for (int j = 0; j < 4; j++) acc[i][j] = 0.f;

    float4 aR[NA], bR;
#pragma unroll
    for (int u = 0; u < NA; u++)
        aR[u] = *(const float4*)(wrow + akb + 4 * u);
    bR = *(const float4*)(bptr);
#pragma unroll
    for (int u = 0; u < NA; u++) {
        As[0][akb + 4 * u + 0][arow] = aR[u].x;
        As[0][akb + 4 * u + 1][arow] = aR[u].y;
        As[0][akb + 4 * u + 2][arow] = aR[u].z;
        As[0][akb + 4 * u + 3][arow] = aR[u].w;
    }
    *(float4*)&Bs[0][brow][bcol] = bR;
    __syncthreads();

    int cur = 0;
    for (int k0 = 0; k0 < Cdim; k0 += 16) {
        bool nxt = (k0 + 16) < Cdim;
        if (nxt) {
#pragma unroll
            for (int u = 0; u < NA; u++)
                aR[u] = *(const float4*)(wrow + k0 + 16 + akb + 4 * u);
            bR = *(const float4*)(bptr + (size_t)(k0 + 16) * HW_);
        }
#pragma unroll
        for (int kk = 0; kk < 16; kk++) {
            float a[TM];
#pragma unroll
            for (int v = 0; v < NA; v++)
                *(float4*)&a[4 * v] = *(const float4*)&As[cur][kk][ty * TM + 4 * v];
            float4 b4 = *(const float4*)&Bs[cur][kk][tx * 4];
#pragma unroll
            for (int i = 0; i < TM; i++) {
                acc[i][0] = fmaf(a[i], b4.x, acc[i][0]);
                acc[i][1] = fmaf(a[i], b4.y, acc[i][1]);
                acc[i][2] = fmaf(a[i], b4.z, acc[i][2]);
                acc[i][3] = fmaf(a[i], b4.w, acc[i][3]);
            }
        }
        if (nxt) {
            int s = cur ^ 1;
#pragma unroll
            for (int u = 0; u < NA; u++) {
                As[s][akb + 4 * u + 0][arow] = aR[u].x;
                As[s][akb + 4 * u + 1][arow] = aR[u].y;
                As[s][akb + 4 * u + 2][arow] = aR[u].z;
                As[s][akb + 4 * u + 3][arow] = aR[u].w;
            }
            *(float4*)&Bs[s][brow][bcol] = bR;
            __syncthreads();
            cur = s;
        }
    }

#pragma unroll
    for (int i = 0; i < TM; i++) {
        int oc2 = ocBase + ty * TM + i;
        float bo = (oc2 < split) ? bias1[oc2] : bias2[oc2 - split];
        float4 r = make_float4(acc[i][0] + bo, acc[i][1] + bo,
                               acc[i][2] + bo, acc[i][3] + bo);
        *(float4*)&Outb[(size_t)oc2 * HW_ + pBase + tx * 4] = r;
    }
}

// ---------------------------------------------------------------------------
// Attention v4: 4 pixels per THREAD-PAIR row-split.
// The j-softmax is independent per window row i, and the aggregation sums
// over i — so adjacent lanes split the 7 rows (even lane: i=0..3, odd lane:
// i=4..6), each accumulates a partial acc[8][4], then the pair combines via
// shfl_xor(1) and splits the 8 group-stores (even: g0..3, odd: g4..7).
// This halves live register state vs v3 (168 regs, occ 11%) -> 2 blocks/SM.
// Masking identical to v3: km OOB -> 0 (logit=gp, counted in denominator),
// x OOB -> weight masked to 0.
__global__ void __launch_bounds__(256, 2) attn_kernel(const float* __restrict__ x) {
    int u = blockIdx.x * 256 + threadIdx.x;   // 784*256 = 200704 exactly
    int half = u & 1;
    int v0 = u >> 1;                          // pixel-quad id < 100352
    int xb = v0 % 14;  int v  = v0 / 14;
    int y  = v % 56;   int v2 = v / 56;
    int c  = v2 % 32;  int b  = v2 / 32;
    int tc = xb * 4;

    int cb0 = (tc == 0)  ? 0  : tc - 4;   // clamped load bases (memory-safe)
    int cb2 = (tc == 52) ? 52 : tc + 4;

    // validity of window slots e=0..11 (col = tc-4+e); only e=1..10 used
    float valid[12];
#pragma unroll
    for (int e = 0; e < 12; e++) {
        int col = tc - 4 + e;
        valid[e] = (col >= 0 && col < W_) ? 1.f : 0.f;
    }

    const float* kmp = g_kmqm + (size_t)(b * 64 + c) * HW_;
    float4 q4 = *(const float4*)(g_kmqm + (size_t)(b * 64 + 32 + c) * HW_ + y * W_ + tc);
    float q[4] = {q4.x, q4.y, q4.z, q4.w};
    const float* gpc = g_gpk + c * 49;
    const float* xb0 = x + (size_t)(b * C_ + c) * HW_;   // group stride 32*HW_

    float acc[8][4];
#pragma unroll
    for (int g = 0; g < 8; g++)
#pragma unroll
        for (int px = 0; px < 4; px++) acc[g][px] = 0.f;

    // Rows for this half: even lane i = 0..3, odd lane i = 4..6 (k=3 skipped)
#pragma unroll
    for (int k = 0; k < 4; k++) {
        int i = half * 4 + k;
        if (i >= 7) continue;
        int yy = y + i - 3;
        if ((unsigned)yy >= (unsigned)H_) continue;   // whole row zero-padded
        int rb = yy * W_;

        float4 k0 = *(const float4*)(kmp + rb + cb0);
        float4 k1 = *(const float4*)(kmp + rb + tc);
        float4 k2 = *(const float4*)(kmp + rb + cb2);
        float km[12] = {k0.x, k0.y, k0.z, k0.w, k1.x, k1.y, k1.z, k1.w,
                        k2.x, k2.y, k2.z, k2.w};
#pragma unroll
        for (int e = 1; e < 11; e++) km[e] *= valid[e];

        float w[4][7], s[4] = {0.f, 0.f, 0.f, 0.f};
#pragma unroll
        for (int j = 0; j < 7; j++) {
            float gp = gpc[i * 7 + j];
#pragma unroll
            for (int px = 0; px < 4; px++) {
                float wv = __expf(fmaf(km[px + j + 1], q[px], gp));
                w[px][j] = wv;
                s[px] += wv;
            }
        }
        float inv[4];
#pragma unroll
        for (int px = 0; px < 4; px++) inv[px] = __frcp_rn(s[px]);
#pragma unroll
        for (int j = 0; j < 7; j++)
#pragma unroll
            for (int px = 0; px < 4; px++)
                w[px][j] *= inv[px] * valid[px + j + 1];

#pragma unroll
        for (int g = 0; g < 8; g++) {
            const float* xr = xb0 + (size_t)g * 32 * HW_ + rb;
            float4 x0 = *(const float4*)(xr + cb0);
            float4 x1 = *(const float4*)(xr + tc);
            float4 x2 = *(const float4*)(xr + cb2);
            float xw[12] = {x0.x, x0.y, x0.z, x0.w, x1.x, x1.y, x1.z, x1.w,
                            x2.x, x2.y, x2.z, x2.w};
#pragma unroll
            for (int j = 0; j < 7; j++)
#pragma unroll
                for (int px = 0; px < 4; px++)
                    acc[g][px] = fmaf(w[px][j], xw[px + j + 1], acc[g][px]);
        }
    }

    // Pair-combine partial row sums (lanes u, u^1 hold the two halves)
#pragma unroll
    for (int g = 0; g < 8; g++)
#pragma unroll
        for (int px = 0; px < 4; px++)
            acc[g][px] += __shfl_xor_sync(0xFFFFFFFFu, acc[g][px], 1);

    // Split the 8 group-stores across the pair
    float* pr = g_pre + (size_t)(b * C_ + c) * HW_ + y * W_ + tc;
    int gb = half * 4;
#pragma unroll
    for (int gg = 0; gg < 4; gg++) {
        int g = gb + gg;
        *(float4*)(pr + (size_t)g * 32 * HW_) =
            make_float4(acc[g][0], acc[g][1], acc[g][2], acc[g][3]);
    }
}

// ---------------------------------------------------------------------------
// Split w_f into bf16 hi/lo
__global__ void wsplit_kernel(const float* __restrict__ wf) {
    int i = blockIdx.x * 256 + threadIdx.x;
    float v = wf[i];
    __nv_bfloat16 h = __float2bfloat16(v);
    g_wf_hi[i] = h;
    g_wf_lo[i] = __float2bfloat16(v - __bfloat162float(h));
}

// ---------------------------------------------------------------------------
// Transpose-convert: g_pre (B,C,HW) fp32 -> g_pret_{hi,lo} (n, c) bf16
__global__ void __launch_bounds__(256) tconv_kernel() {
    __shared__ float s[32][33];
    int b = blockIdx.z;
    int p0 = blockIdx.x * 32, c0 = blockIdx.y * 32;
    int t = threadIdx.x, r = t >> 3, q = t & 7;

    float4 v = *(const float4*)&g_pre[((size_t)b * C_ + c0 + r) * HW_ + p0 + q * 4];
    s[r][q * 4 + 0] = v.x; s[r][q * 4 + 1] = v.y;
    s[r][q * 4 + 2] = v.z; s[r][q * 4 + 3] = v.w;
    __syncthreads();

    float a0 = s[q * 4 + 0][r], a1 = s[q * 4 + 1][r];
    float a2 = s[q * 4 + 2][r], a3 = s[q * 4 + 3][r];
    __nv_bfloat16 h0 = __float2bfloat16(a0), h1 = __float2bfloat16(a1);
    __nv_bfloat16 h2 = __float2bfloat16(a2), h3 = __float2bfloat16(a3);
    __nv_bfloat16 l0 = __float2bfloat16(a0 - __bfloat162float(h0));
    __nv_bfloat16 l1 = __float2bfloat16(a1 - __bfloat162float(h1));
    __nv_bfloat16 l2 = __float2bfloat16(a2 - __bfloat162float(h2));
    __nv_bfloat16 l3 = __float2bfloat16(a3 - __bfloat162float(h3));

    size_t off = ((size_t)(b * HW_ + p0 + r)) * C_ + c0 + q * 4;
    uint2 uh, ul;
    uh.x = ((uint32_t)__bfloat16_as_ushort(h1) << 16) | __bfloat16_as_ushort(h0);
    uh.y = ((uint32_t)__bfloat16_as_ushort(h3) << 16) | __bfloat16_as_ushort(h2);
    ul.x = ((uint32_t)__bfloat16_as_ushort(l1) << 16) | __bfloat16_as_ushort(l0);
    ul.y = ((uint32_t)__bfloat16_as_ushort(l3) << 16) | __bfloat16_as_ushort(l2);
    *(uint2*)(g_pret_hi + off) = uh;
    *(uint2*)(g_pret_lo + off) = ul;
}

// ---------------------------------------------------------------------------
// Final 1x1 conv via mma.sync bf16.  out[oc, n] = sum_c Wsplit[oc,c]*Psplit[n,c].
// 3 bf16 passes (hi.hi + hi.lo + lo.hi), fp32 accum, 12 K64 stages.
__global__ void __launch_bounds__(256) mma_final(const float* __restrict__ bias,
                                                 float* __restrict__ out) {
    __shared__ __align__(128) __nv_bfloat16 sm[16384];   // A: [0,8192) elems, B: [8192,16384)
    uint32_t aT = smem_u32(sm);
    uint32_t bT = aT + 16384u;

    int tid = threadIdx.x;
    int wid = tid >> 5, l = tid & 31;
    int warp_m = wid & 3, warp_n = wid >> 2;
    int m0w = warp_m * 32, n0w = warp_n * 64;
    int ocBase = blockIdx.y * 128;
    int n0 = blockIdx.x * 128;

    int lrow = l & 15, lsel = l >> 4;

    float acc[2][8][4];
#pragma unroll
    for (int mt = 0; mt < 2; mt++)
#pragma unroll
        for (int nt = 0; nt < 8; nt++)
#pragma unroll
            for (int q = 0; q < 4; q++) acc[mt][nt][q] = 0.f;

    uint32_t arow_off[2], axor[2], brow_off[4], bxor[4];
#pragma unroll
    for (int mt = 0; mt < 2; mt++) {
        int row = m0w + mt * 16 + lrow;
        arow_off[mt] = (uint32_t)(row * 128);
        axor[mt] = (uint32_t)((row & 7) << 4);
    }
#pragma unroll
    for (int nt = 0; nt < 4; nt++) {
        int row = n0w + nt * 16 + lrow;
        brow_off[nt] = (uint32_t)(row * 128);
        bxor[nt] = (uint32_t)((row & 7) << 4);
    }

    uint4 aReg[4], bReg[4];
    uint32_t stoff[4];
#pragma unroll
    for (int it = 0; it < 4; it++) {
        int u = tid + it * 256;
        int r = u >> 3, cu = u & 7;
        stoff[it] = (uint32_t)(r * 128) + (uint32_t)((cu * 16) ^ ((r & 7) << 4));
    }

    auto fetch = [&](int s) {
        int pass = s >> 2, kc = s & 3;
        const __nv_bfloat16* Wp = (pass == 2) ? g_wf_lo : g_wf_hi;
        const __nv_bfloat16* Pp = (pass == 1) ? g_pret_lo : g_pret_hi;
#pragma unroll
        for (int it = 0; it < 4; it++) {
            int u = tid + it * 256;
            int r = u >> 3, cu = u & 7;
            aReg[it] = *(const uint4*)(Wp + (size_t)(ocBase + r) * C_ + kc * 64 + cu * 8);
            bReg[it] = *(const uint4*)(Pp + (size_t)(n0 + r) * C_ + kc * 64 + cu * 8);
        }
    };
    auto store_stage = [&]() {
#pragma unroll
        for (int it = 0; it < 4; it++) {
            *(uint4*)((char*)sm + stoff[it]) = aReg[it];
            *(uint4*)((char*)sm + 16384 + stoff[it]) = bReg[it];
        }
    };

    fetch(0);
    store_stage();
    __syncthreads();

    for (int s = 0; s < 12; s++) {
        if (s + 1 < 12) fetch(s + 1);

#pragma unroll
        for (int k16 = 0; k16 < 4; k16++) {
            uint32_t koff = (uint32_t)(k16 * 32 + lsel * 16);
            uint32_t a[2][4], br[4][4];
#pragma unroll
            for (int mt = 0; mt < 2; mt++)
                ldsm_x4(aT + arow_off[mt] + (koff ^ axor[mt]),
                        a[mt][0], a[mt][1], a[mt][2], a[mt][3]);
#pragma unroll
            for (int nt = 0; nt < 4; nt++)
                ldsm_x4(bT + brow_off[nt] + (koff ^ bxor[nt]),
                        br[nt][0], br[nt][1], br[nt][2], br[nt][3]);
#pragma unroll
            for (int mt = 0; mt < 2; mt++)
#pragma unroll
                for (int n8 = 0; n8 < 8; n8++) {
                    int nt = n8 >> 1, sub = n8 & 1;
                    mma16816(acc[mt][n8], a[mt], br[nt][sub], br[nt][sub + 2]);
                }
        }

        if (s + 1 < 12) {
            __syncthreads();
            store_stage();
            __syncthreads();
        }
    }

    int rowg = l >> 2, colp = (l & 3) * 2;
#pragma unroll
    for (int mt = 0; mt < 2; mt++) {
        int oc  = ocBase + m0w + mt * 16 + rowg;
        int oc2 = oc + 8;
        float b0v = bias[oc], b1v = bias[oc2];
#pragma unroll
        for (int n8 = 0; n8 < 8; n8++) {
            int n = n0 + n0w + n8 * 8 + colp;
            int bb = n / HW_;
            int p = n - bb * HW_;
            *(float2*)&out[((size_t)bb * C_ + oc) * HW_ + p] =
                make_float2(acc[mt][n8][0] + b0v, acc[mt][n8][1] + b0v);
            *(float2*)&out[((size_t)bb * C_ + oc2) * HW_ + p] =
                make_float2(acc[mt][n8][2] + b1v, acc[mt][n8][3] + b1v);
        }
    }
}

// ---------------------------------------------------------------------------
extern "C" void kernel_launch(void* const* d_in, const int* in_sizes, int n_in,
                              void* d_out, int out_size) {
    const float* x    = (const float*)d_in[0];
    const float* w_k  = (const float*)d_in[1];
    const float* b_k  = (const float*)d_in[2];
    const float* w_q  = (const float*)d_in[3];
    const float* b_q  = (const float*)d_in[4];
    const float* w_g1 = (const float*)d_in[5];
    const float* b_g1 = (const float*)d_in[6];
    const float* w_g2 = (const float*)d_in[7];
    const float* b_g2 = (const float*)d_in[8];
    const float* w_f  = (const float*)d_in[9];
    const float* b_f  = (const float*)d_in[10];
    float* out = (float*)d_out;

    float* kmqm;
    cudaGetSymbolAddress((void**)&kmqm, g_kmqm);

    gpk_kernel<<<7, 256>>>(w_g1, b_g1, w_g2, b_g2);
    wsplit_kernel<<<256, 256>>>(w_f);
    gemm2<64><<<dim3(HW_ / 64, 1, B_), 256>>>(w_k, w_q, 32, b_k, b_q, x, kmqm, C_, 64);
    // attention: thread-pair row-split, 2*B*CQ*H*(W/4) = 200704 threads
    attn_kernel<<<784, 256>>>(x);
    tconv_kernel<<<dim3(HW_ / 32, C_ / 32, B_), 256>>>();
    mma_final<<<dim3(N_TOT / 128, C_ / 128, 1), 256>>>(b_f, out);
}

// round 16
// speedup vs baseline: 1.1183x; 1.1183x over previous
#include <cuda_runtime.h>
#include <cuda_bf16.h>
#include <cstdint>

// Problem constants
#define B_    4
#define C_    256
#define CQ_   32
#define MID_  16
#define H_    56
#define W_    56
#define HW_   3136     // 56*56
#define N_TOT 12544    // B_*HW_

// Scratch (allocation-free: __device__ globals). 16B-aligned for uint4.
__device__ float g_gpk[CQ_ * 49];
__device__ float g_kmqm[B_ * 64 * HW_];
__device__ float g_pre [B_ * C_ * HW_];   // partial: window rows 0..3
__device__ float g_preB[B_ * C_ * HW_];   // partial: window rows 4..6
__device__ __align__(16) __nv_bfloat16 g_pret_hi[N_TOT * C_];   // (n, c) K-major
__device__ __align__(16) __nv_bfloat16 g_pret_lo[N_TOT * C_];
__device__ __align__(16) __nv_bfloat16 g_wf_hi[C_ * C_];
__device__ __align__(16) __nv_bfloat16 g_wf_lo[C_ * C_];

__device__ __forceinline__ uint32_t smem_u32(const void* p) {
    uint32_t a;
    asm("{ .reg .u64 t; cvta.to.shared.u64 t, %1; cvt.u32.u64 %0, t; }" : "=r"(a) : "l"(p));
    return a;
}
__device__ __forceinline__ void ldsm_x4(uint32_t addr, uint32_t& r0, uint32_t& r1,
                                        uint32_t& r2, uint32_t& r3) {
    asm volatile("ldmatrix.sync.aligned.m8n8.x4.shared.b16 {%0,%1,%2,%3}, [%4];"
                 : "=r"(r0), "=r"(r1), "=r"(r2), "=r"(r3) : "r"(addr));
}
__device__ __forceinline__ void mma16816(float* d, const uint32_t* a, uint32_t b0, uint32_t b1) {
    asm volatile(
        "mma.sync.aligned.m16n8k16.row.col.f32.bf16.bf16.f32 "
        "{%0,%1,%2,%3}, {%4,%5,%6,%7}, {%8,%9}, {%0,%1,%2,%3};"
        : "+f"(d[0]), "+f"(d[1]), "+f"(d[2]), "+f"(d[3])
        : "r"(a[0]), "r"(a[1]), "r"(a[2]), "r"(a[3]), "r"(b0), "r"(b1));
}

// ---------------------------------------------------------------------------
// Geometry prior
__global__ void gpk_kernel(const float* __restrict__ wg1, const float* __restrict__ bg1,
                           const float* __restrict__ wg2, const float* __restrict__ bg2) {
    int idx = blockIdx.x * 256 + threadIdx.x;
    if (idx >= CQ_ * 49) return;
    int c = idx / 49, r = idx % 49, i = r / 7, j = r % 7;
    float xp = (float)(j - 3);
    float yp = (float)(3 - i);
    float acc = bg2[c];
#pragma unroll
    for (int o = 0; o < MID_; o++) {
        float g1 = fmaf(wg1[o * 2 + 0], xp, fmaf(wg1[o * 2 + 1], yp, bg1[o]));
        g1 = fmaxf(g1, 0.f);
        acc = fmaf(wg2[c * MID_ + o], g1, acc);
    }
    g_gpk[idx] = acc;
}

// ---------------------------------------------------------------------------
// Double-buffered SGEMM for km/qm (BM=64)
template<int BM>
__global__ void __launch_bounds__(256) gemm2(
    const float* __restrict__ W1, const float* __restrict__ W2, int split,
    const float* __restrict__ bias1, const float* __restrict__ bias2,
    const float* __restrict__ In, float* __restrict__ Out, int Cdim, int OC) {
    constexpr int TM = BM / 16;
    constexpr int NA = TM / 4;
    __shared__ float As[2][16][BM];
    __shared__ float Bs[2][16][64];

    int b = blockIdx.z;
    const float* Inb = In + (size_t)b * Cdim * HW_;
    float* Outb = Out + (size_t)b * OC * HW_;
    int ocBase = blockIdx.y * BM;
    int pBase  = blockIdx.x * 64;

    int tid = threadIdx.x;
    int tx = tid & 15, ty = tid >> 4;

    int arow, akb;
    if (BM == 128) { arow = tid >> 1; akb = (tid & 1) * 8; }
    else           { arow = tid >> 2; akb = (tid & 3) * 4; }
    int oc = ocBase + arow;
    const float* wrow = (oc < split) ? (W1 + (size_t)oc * Cdim)
                                     : (W2 + (size_t)(oc - split) * Cdim);
    int brow = tid >> 4, bcol = (tid & 15) * 4;
    const float* bptr = Inb + (size_t)brow * HW_ + pBase + bcol;

    float acc[TM][4];
#pragma unroll
    for (int i = 0; i < TM; i++)
#pragma unroll
        for (int j = 0; j < 4; j++) acc[i][j] = 0.f;

    float4 aR[NA], bR;
#pragma unroll
    for (int u = 0; u < NA; u++)
        aR[u] = *(const float4*)(wrow + akb + 4 * u);
    bR = *(const float4*)(bptr);
#pragma unroll
    for (int u = 0; u < NA; u++) {
        As[0][akb + 4 * u + 0][arow] = aR[u].x;
        As[0][akb + 4 * u + 1][arow] = aR[u].y;
        As[0][akb + 4 * u + 2][arow] = aR[u].z;
        As[0][akb + 4 * u + 3][arow] = aR[u].w;
    }
    *(float4*)&Bs[0][brow][bcol] = bR;
    __syncthreads();

    int cur = 0;
    for (int k0 = 0; k0 < Cdim; k0 += 16) {
        bool nxt = (k0 + 16) < Cdim;
        if (nxt) {
#pragma unroll
            for (int u = 0; u < NA; u++)
                aR[u] = *(const float4*)(wrow + k0 + 16 + akb + 4 * u);
            bR = *(const float4*)(bptr + (size_t)(k0 + 16) * HW_);
        }
#pragma unroll
        for (int kk = 0; kk < 16; kk++) {
            float a[TM];
#pragma unroll
            for (int v = 0; v < NA; v++)
                *(float4*)&a[4 * v] = *(const float4*)&As[cur][kk][ty * TM + 4 * v];
            float4 b4 = *(const float4*)&Bs[cur][kk][tx * 4];
#pragma unroll
            for (int i = 0; i < TM; i++) {
                acc[i][0] = fmaf(a[i], b4.x, acc[i][0]);
                acc[i][1] = fmaf(a[i], b4.y, acc[i][1]);
                acc[i][2] = fmaf(a[i], b4.z, acc[i][2]);
                acc[i][3] = fmaf(a[i], b4.w, acc[i][3]);
            }
        }
        if (nxt) {
            int s = cur ^ 1;
#pragma unroll
            for (int u = 0; u < NA; u++) {
                As[s][akb + 4 * u + 0][arow] = aR[u].x;
                As[s][akb + 4 * u + 1][arow] = aR[u].y;
                As[s][akb + 4 * u + 2][arow] = aR[u].z;
                As[s][akb + 4 * u + 3][arow] = aR[u].w;
            }
            *(float4*)&Bs[s][brow][bcol] = bR;
            __syncthreads();
            cur = s;
        }
    }

#pragma unroll
    for (int i = 0; i < TM; i++) {
        int oc2 = ocBase + ty * TM + i;
        float bo = (oc2 < split) ? bias1[oc2] : bias2[oc2 - split];
        float4 r = make_float4(acc[i][0] + bo, acc[i][1] + bo,
                               acc[i][2] + bo, acc[i][3] + bo);
        *(float4*)&Outb[(size_t)oc2 * HW_ + pBase + tx * 4] = r;
    }
}

// ---------------------------------------------------------------------------
// Attention v5: 4 pixels/thread (v3 layout — warp lanes = consecutive quads,
// coalesced float4 loads), window rows split across blockIdx.y:
//   blockIdx.y = 0 -> rows i = 0..3 -> partial sums into g_pre
//   blockIdx.y = 1 -> rows i = 4..6 -> partial sums into g_preB
// tconv adds the two partials. Halved per-thread row count cuts live register
// state (v3: 168 regs, occ 11%) so (256,2) gives 2 blocks/SM WITHOUT the
// v4 intra-warp row interleave that broke coalescing (L2 4.6%->33.9%).
// Masking as v3: km OOB -> 0 (logit=gp, counted in denominator), x OOB ->
// weight masked to 0.
__global__ void __launch_bounds__(256, 2) attn_kernel(const float* __restrict__ x) {
    int half = blockIdx.y;
    int u = blockIdx.x * 256 + threadIdx.x;   // quad id < 100352 (392*256)
    int xb = u % 14;  int v  = u / 14;
    int y  = v % 56;  int v2 = v / 56;
    int c  = v2 % 32; int b  = v2 / 32;
    int tc = xb * 4;

    int cb0 = (tc == 0)  ? 0  : tc - 4;   // clamped load bases (memory-safe)
    int cb2 = (tc == 52) ? 52 : tc + 4;

    // validity of window slots e=0..11 (col = tc-4+e); only e=1..10 used
    float valid[12];
#pragma unroll
    for (int e = 0; e < 12; e++) {
        int col = tc - 4 + e;
        valid[e] = (col >= 0 && col < W_) ? 1.f : 0.f;
    }

    const float* kmp = g_kmqm + (size_t)(b * 64 + c) * HW_;
    float4 q4 = *(const float4*)(g_kmqm + (size_t)(b * 64 + 32 + c) * HW_ + y * W_ + tc);
    float q[4] = {q4.x, q4.y, q4.z, q4.w};
    const float* gpc = g_gpk + c * 49;
    const float* xb0 = x + (size_t)(b * C_ + c) * HW_;   // group stride 32*HW_

    float acc[8][4];
#pragma unroll
    for (int g = 0; g < 8; g++)
#pragma unroll
        for (int px = 0; px < 4; px++) acc[g][px] = 0.f;

    // Rows for this block-half: half0 -> i=0..3, half1 -> i=4..6
#pragma unroll
    for (int k = 0; k < 4; k++) {
        int i = half * 4 + k;
        if (i >= 7) continue;
        int yy = y + i - 3;
        if ((unsigned)yy >= (unsigned)H_) continue;   // whole row zero-padded
        int rb = yy * W_;

        float4 k0 = *(const float4*)(kmp + rb + cb0);
        float4 k1 = *(const float4*)(kmp + rb + tc);
        float4 k2 = *(const float4*)(kmp + rb + cb2);
        float km[12] = {k0.x, k0.y, k0.z, k0.w, k1.x, k1.y, k1.z, k1.w,
                        k2.x, k2.y, k2.z, k2.w};
#pragma unroll
        for (int e = 1; e < 11; e++) km[e] *= valid[e];

        float w[4][7], s[4] = {0.f, 0.f, 0.f, 0.f};
#pragma unroll
        for (int j = 0; j < 7; j++) {
            float gp = gpc[i * 7 + j];
#pragma unroll
            for (int px = 0; px < 4; px++) {
                float wv = __expf(fmaf(km[px + j + 1], q[px], gp));
                w[px][j] = wv;
                s[px] += wv;
            }
        }
        float inv[4];
#pragma unroll
        for (int px = 0; px < 4; px++) inv[px] = __frcp_rn(s[px]);
#pragma unroll
        for (int j = 0; j < 7; j++)
#pragma unroll
            for (int px = 0; px < 4; px++)
                w[px][j] *= inv[px] * valid[px + j + 1];

#pragma unroll
        for (int g = 0; g < 8; g++) {
            const float* xr = xb0 + (size_t)g * 32 * HW_ + rb;
            float4 x0 = *(const float4*)(xr + cb0);
            float4 x1 = *(const float4*)(xr + tc);
            float4 x2 = *(const float4*)(xr + cb2);
            float xw[12] = {x0.x, x0.y, x0.z, x0.w, x1.x, x1.y, x1.z, x1.w,
                            x2.x, x2.y, x2.z, x2.w};
#pragma unroll
            for (int j = 0; j < 7; j++)
#pragma unroll
                for (int px = 0; px < 4; px++)
                    acc[g][px] = fmaf(w[px][j], xw[px + j + 1], acc[g][px]);
        }
    }

    float* prbase = half ? g_preB : g_pre;
    float* pr = prbase + (size_t)(b * C_ + c) * HW_ + y * W_ + tc;
#pragma unroll
    for (int g = 0; g < 8; g++)
        *(float4*)(pr + (size_t)g * 32 * HW_) =
            make_float4(acc[g][0], acc[g][1], acc[g][2], acc[g][3]);
}

// ---------------------------------------------------------------------------
// Split w_f into bf16 hi/lo
__global__ void wsplit_kernel(const float* __restrict__ wf) {
    int i = blockIdx.x * 256 + threadIdx.x;
    float v = wf[i];
    __nv_bfloat16 h = __float2bfloat16(v);
    g_wf_hi[i] = h;
    g_wf_lo[i] = __float2bfloat16(v - __bfloat162float(h));
}

// ---------------------------------------------------------------------------
// Transpose-convert: (g_pre + g_preB) (B,C,HW) fp32 -> g_pret_{hi,lo} (n,c) bf16
__global__ void __launch_bounds__(256) tconv_kernel() {
    __shared__ float s[32][33];
    int b = blockIdx.z;
    int p0 = blockIdx.x * 32, c0 = blockIdx.y * 32;
    int t = threadIdx.x, r = t >> 3, q = t & 7;

    size_t ioff = ((size_t)b * C_ + c0 + r) * HW_ + p0 + q * 4;
    float4 vA = *(const float4*)&g_pre[ioff];
    float4 vB = *(const float4*)&g_preB[ioff];
    s[r][q * 4 + 0] = vA.x + vB.x; s[r][q * 4 + 1] = vA.y + vB.y;
    s[r][q * 4 + 2] = vA.z + vB.z; s[r][q * 4 + 3] = vA.w + vB.w;
    __syncthreads();

    float a0 = s[q * 4 + 0][r], a1 = s[q * 4 + 1][r];
    float a2 = s[q * 4 + 2][r], a3 = s[q * 4 + 3][r];
    __nv_bfloat16 h0 = __float2bfloat16(a0), h1 = __float2bfloat16(a1);
    __nv_bfloat16 h2 = __float2bfloat16(a2), h3 = __float2bfloat16(a3);
    __nv_bfloat16 l0 = __float2bfloat16(a0 - __bfloat162float(h0));
    __nv_bfloat16 l1 = __float2bfloat16(a1 - __bfloat162float(h1));
    __nv_bfloat16 l2 = __float2bfloat16(a2 - __bfloat162float(h2));
    __nv_bfloat16 l3 = __float2bfloat16(a3 - __bfloat162float(h3));

    size_t off = ((size_t)(b * HW_ + p0 + r)) * C_ + c0 + q * 4;
    uint2 uh, ul;
    uh.x = ((uint32_t)__bfloat16_as_ushort(h1) << 16) | __bfloat16_as_ushort(h0);
    uh.y = ((uint32_t)__bfloat16_as_ushort(h3) << 16) | __bfloat16_as_ushort(h2);
    ul.x = ((uint32_t)__bfloat16_as_ushort(l1) << 16) | __bfloat16_as_ushort(l0);
    ul.y = ((uint32_t)__bfloat16_as_ushort(l3) << 16) | __bfloat16_as_ushort(l2);
    *(uint2*)(g_pret_hi + off) = uh;
    *(uint2*)(g_pret_lo + off) = ul;
}

// ---------------------------------------------------------------------------
// Final 1x1 conv via mma.sync bf16.  out[oc, n] = sum_c Wsplit[oc,c]*Psplit[n,c].
// 3 bf16 passes (hi.hi + hi.lo + lo.hi), fp32 accum, 12 K64 stages.
__global__ void __launch_bounds__(256) mma_final(const float* __restrict__ bias,
                                                 float* __restrict__ out) {
    __shared__ __align__(128) __nv_bfloat16 sm[16384];   // A: [0,8192) elems, B: [8192,16384)
    uint32_t aT = smem_u32(sm);
    uint32_t bT = aT + 16384u;

    int tid = threadIdx.x;
    int wid = tid >> 5, l = tid & 31;
    int warp_m = wid & 3, warp_n = wid >> 2;
    int m0w = warp_m * 32, n0w = warp_n * 64;
    int ocBase = blockIdx.y * 128;
    int n0 = blockIdx.x * 128;

    int lrow = l & 15, lsel = l >> 4;

    float acc[2][8][4];
#pragma unroll
    for (int mt = 0; mt < 2; mt++)
#pragma unroll
        for (int nt = 0; nt < 8; nt++)
#pragma unroll
            for (int q = 0; q < 4; q++) acc[mt][nt][q] = 0.f;

    uint32_t arow_off[2], axor[2], brow_off[4], bxor[4];
#pragma unroll
    for (int mt = 0; mt < 2; mt++) {
        int row = m0w + mt * 16 + lrow;
        arow_off[mt] = (uint32_t)(row * 128);
        axor[mt] = (uint32_t)((row & 7) << 4);
    }
#pragma unroll
    for (int nt = 0; nt < 4; nt++) {
        int row = n0w + nt * 16 + lrow;
        brow_off[nt] = (uint32_t)(row * 128);
        bxor[nt] = (uint32_t)((row & 7) << 4);
    }

    uint4 aReg[4], bReg[4];
    uint32_t stoff[4];
#pragma unroll
    for (int it = 0; it < 4; it++) {
        int u = tid + it * 256;
        int r = u >> 3, cu = u & 7;
        stoff[it] = (uint32_t)(r * 128) + (uint32_t)((cu * 16) ^ ((r & 7) << 4));
    }

    auto fetch = [&](int s) {
        int pass = s >> 2, kc = s & 3;
        const __nv_bfloat16* Wp = (pass == 2) ? g_wf_lo : g_wf_hi;
        const __nv_bfloat16* Pp = (pass == 1) ? g_pret_lo : g_pret_hi;
#pragma unroll
        for (int it = 0; it < 4; it++) {
            int u = tid + it * 256;
            int r = u >> 3, cu = u & 7;
            aReg[it] = *(const uint4*)(Wp + (size_t)(ocBase + r) * C_ + kc * 64 + cu * 8);
            bReg[it] = *(const uint4*)(Pp + (size_t)(n0 + r) * C_ + kc * 64 + cu * 8);
        }
    };
    auto store_stage = [&]() {
#pragma unroll
        for (int it = 0; it < 4; it++) {
            *(uint4*)((char*)sm + stoff[it]) = aReg[it];
            *(uint4*)((char*)sm + 16384 + stoff[it]) = bReg[it];
        }
    };

    fetch(0);
    store_stage();
    __syncthreads();

    for (int s = 0; s < 12; s++) {
        if (s + 1 < 12) fetch(s + 1);

#pragma unroll
        for (int k16 = 0; k16 < 4; k16++) {
            uint32_t koff = (uint32_t)(k16 * 32 + lsel * 16);
            uint32_t a[2][4], br[4][4];
#pragma unroll
            for (int mt = 0; mt < 2; mt++)
                ldsm_x4(aT + arow_off[mt] + (koff ^ axor[mt]),
                        a[mt][0], a[mt][1], a[mt][2], a[mt][3]);
#pragma unroll
            for (int nt = 0; nt < 4; nt++)
                ldsm_x4(bT + brow_off[nt] + (koff ^ bxor[nt]),
                        br[nt][0], br[nt][1], br[nt][2], br[nt][3]);
#pragma unroll
            for (int mt = 0; mt < 2; mt++)
#pragma unroll
                for (int n8 = 0; n8 < 8; n8++) {
                    int nt = n8 >> 1, sub = n8 & 1;
                    mma16816(acc[mt][n8], a[mt], br[nt][sub], br[nt][sub + 2]);
                }
        }

        if (s + 1 < 12) {
            __syncthreads();
            store_stage();
            __syncthreads();
        }
    }

    int rowg = l >> 2, colp = (l & 3) * 2;
#pragma unroll
    for (int mt = 0; mt < 2; mt++) {
        int oc  = ocBase + m0w + mt * 16 + rowg;
        int oc2 = oc + 8;
        float b0v = bias[oc], b1v = bias[oc2];
#pragma unroll
        for (int n8 = 0; n8 < 8; n8++) {
            int n = n0 + n0w + n8 * 8 + colp;
            int bb = n / HW_;
            int p = n - bb * HW_;
            *(float2*)&out[((size_t)bb * C_ + oc) * HW_ + p] =
                make_float2(acc[mt][n8][0] + b0v, acc[mt][n8][1] + b0v);
            *(float2*)&out[((size_t)bb * C_ + oc2) * HW_ + p] =
                make_float2(acc[mt][n8][2] + b1v, acc[mt][n8][3] + b1v);
        }
    }
}

// ---------------------------------------------------------------------------
extern "C" void kernel_launch(void* const* d_in, const int* in_sizes, int n_in,
                              void* d_out, int out_size) {
    const float* x    = (const float*)d_in[0];
    const float* w_k  = (const float*)d_in[1];
    const float* b_k  = (const float*)d_in[2];
    const float* w_q  = (const float*)d_in[3];
    const float* b_q  = (const float*)d_in[4];
    const float* w_g1 = (const float*)d_in[5];
    const float* b_g1 = (const float*)d_in[6];
    const float* w_g2 = (const float*)d_in[7];
    const float* b_g2 = (const float*)d_in[8];
    const float* w_f  = (const float*)d_in[9];
    const float* b_f  = (const float*)d_in[10];
    float* out = (float*)d_out;

    float* kmqm;
    cudaGetSymbolAddress((void**)&kmqm, g_kmqm);

    gpk_kernel<<<7, 256>>>(w_g1, b_g1, w_g2, b_g2);
    wsplit_kernel<<<256, 256>>>(w_f);
    gemm2<64><<<dim3(HW_ / 64, 1, B_), 256>>>(w_k, w_q, 32, b_k, b_q, x, kmqm, C_, 64);
    // attention: v3 layout, rows split across blockIdx.y (0: i=0..3, 1: i=4..6)
    attn_kernel<<<dim3(392, 2), 256>>>(x);
    tconv_kernel<<<dim3(HW_ / 32, C_ / 32, B_), 256>>>();
    mma_final<<<dim3(N_TOT / 128, C_ / 128, 1), 256>>>(b_f, out);
}